// round 5
// baseline (speedup 1.0000x reference)
#include <cuda_runtime.h>
#include <math.h>

#define NN 4
#define CC 64
#define HH 256
#define WW 256
#define OC 18          // G*K*K
#define HW (HH*WW)
#define EPSF 1e-5f

// Scratch (device globals; zero-initialized at load, kept zero by k_stats).
__device__ float g_sigma[(size_t)NN * OC * HW];   // ~18.9 MB
__device__ float g_sum[OC], g_sumsq[OC], g_mean[OC], g_rstd[OC];

#define FMA_F32X2(d, a, b, c) \
    asm("fma.rn.f32x2 %0, %1, %2, %3;" : "=l"(d) : "l"(a), "l"(b), "l"(c))

__device__ __forceinline__ unsigned long long pack2(float v) {
    unsigned long long r;
    asm("mov.b64 %0, {%1, %1};" : "=l"(r) : "r"(__float_as_uint(v)));
    return r;
}
__device__ __forceinline__ float lo2(unsigned long long v) { return __uint_as_float((unsigned)v); }
__device__ __forceinline__ float hi2(unsigned long long v) { return __uint_as_float((unsigned)(v >> 32)); }

// jnp.pad mode='reflect' (mirror, edge not repeated)
__device__ __forceinline__ int refl(int i, int n) {
    return i < 0 ? -i : (i >= n ? 2 * n - 2 - i : i);
}

// ---------------------------------------------------------------------------
// Stage 1: 3x3 conv (64 -> 18 ch, reflect) + BN stats.
// 2 pixels/thread, 9 packed FFMA2 accumulators per pixel, 1024 CTAs for
// occupancy (5 CTAs/SM). acc2[p*9+q] = outputs (2q,2q+1) for pixel p.
// ---------------------------------------------------------------------------

// One tap for 2 pixels: 9 packed weights vs broadcast values va, vb.
#define TAP2(wp, va, vb)                                                       \
    {                                                                          \
        ulonglong2 w01 = *(const ulonglong2*)((wp));                           \
        ulonglong2 w23 = *(const ulonglong2*)((wp) + 4);                       \
        FMA_F32X2(acc2[0],  va, w01.x, acc2[0]);                               \
        FMA_F32X2(acc2[1],  va, w01.y, acc2[1]);                               \
        FMA_F32X2(acc2[2],  va, w23.x, acc2[2]);                               \
        FMA_F32X2(acc2[3],  va, w23.y, acc2[3]);                               \
        FMA_F32X2(acc2[9],  vb, w01.x, acc2[9]);                               \
        FMA_F32X2(acc2[10], vb, w01.y, acc2[10]);                              \
        FMA_F32X2(acc2[11], vb, w23.x, acc2[11]);                              \
        FMA_F32X2(acc2[12], vb, w23.y, acc2[12]);                              \
        ulonglong2 w45 = *(const ulonglong2*)((wp) + 8);                       \
        ulonglong2 w67 = *(const ulonglong2*)((wp) + 12);                      \
        unsigned long long w8 = *(const unsigned long long*)((wp) + 16);       \
        FMA_F32X2(acc2[4],  va, w45.x, acc2[4]);                               \
        FMA_F32X2(acc2[5],  va, w45.y, acc2[5]);                               \
        FMA_F32X2(acc2[6],  va, w67.x, acc2[6]);                               \
        FMA_F32X2(acc2[7],  va, w67.y, acc2[7]);                               \
        FMA_F32X2(acc2[8],  va, w8,    acc2[8]);                               \
        FMA_F32X2(acc2[13], vb, w45.x, acc2[13]);                              \
        FMA_F32X2(acc2[14], vb, w45.y, acc2[14]);                              \
        FMA_F32X2(acc2[15], vb, w67.x, acc2[15]);                              \
        FMA_F32X2(acc2[16], vb, w67.y, acc2[16]);                              \
        FMA_F32X2(acc2[17], vb, w8,    acc2[17]);                              \
    }

// One image row: mid tap first (its float2 load is the critical one),
// then left/right taps whose edge scalars are L1 hits.
#define ROW2(m, el, er, wrow3)                                                 \
    {                                                                          \
        unsigned long long v1 = pack2((m).x), v2 = pack2((m).y);               \
        TAP2((wrow3) + 20, v1, v2)                                             \
        unsigned long long v0 = pack2(el);                                     \
        TAP2((wrow3), v0, v1)                                                  \
        unsigned long long v3 = pack2(er);                                     \
        TAP2((wrow3) + 40, v2, v3)                                             \
    }

__global__ void __launch_bounds__(128, 5) k_conv(const float* __restrict__ y,
                                                 const float* __restrict__ wconv) {
    __shared__ __align__(16) float ws[CC * 9 * 20];   // 46080 B (stride 20, 18 used)
    __shared__ float ssum[OC], ssq[OC];

    int tx = threadIdx.x, ty = threadIdx.y;
    int tid = ty * 32 + tx;

    if (tid < OC) { ssum[tid] = 0.f; ssq[tid] = 0.f; }
    for (int i = tid; i < CC * 9 * OC; i += 128) {
        int o = i % OC, ct = i / OC;
        ws[ct * 20 + o] = wconv[((size_t)o * CC + ct / 9) * 9 + (ct % 9)];
    }
    __syncthreads();

    int w0 = (blockIdx.x * 32 + tx) * 2;
    int h0 = blockIdx.y * 4 + ty;
    int n  = blockIdx.z;

    int rh[3];
#pragma unroll
    for (int i = 0; i < 3; i++) rh[i] = refl(h0 + i - 1, HH);
    int wl = refl(w0 - 1, WW);
    int wr = refl(w0 + 2, WW);

    int om0 = rh[0] * WW + w0, om1 = rh[1] * WW + w0, om2 = rh[2] * WW + w0;
    int ol0 = rh[0] * WW + wl, ol1 = rh[1] * WW + wl, ol2 = rh[2] * WW + wl;
    int or0 = rh[0] * WW + wr, or1 = rh[1] * WW + wr, or2 = rh[2] * WW + wr;

    unsigned long long acc2[18];
#pragma unroll
    for (int p = 0; p < 18; p++) acc2[p] = 0ull;

    const float* yc = y + ((size_t)n * CC) * HW;

#pragma unroll 2
    for (int c = 0; c < CC; c++) {
        float2 m0 = __ldg((const float2*)(yc + om0));
        float2 m1 = __ldg((const float2*)(yc + om1));
        float2 m2 = __ldg((const float2*)(yc + om2));
        float el0 = __ldg(yc + ol0), er0 = __ldg(yc + or0);
        float el1 = __ldg(yc + ol1), er1 = __ldg(yc + or1);
        float el2 = __ldg(yc + ol2), er2 = __ldg(yc + or2);

        const float* wrow = &ws[c * 180];
        ROW2(m0, el0, er0, wrow)
        ROW2(m1, el1, er1, wrow + 60)
        ROW2(m2, el2, er2, wrow + 120)

        yc += HW;
    }

    size_t pix = (size_t)h0 * WW + w0;
#pragma unroll
    for (int o = 0; o < OC; o++) {
        int u = o >> 1;
        float2 vv;
        if (o & 1) vv = make_float2(hi2(acc2[u]), hi2(acc2[9 + u]));
        else       vv = make_float2(lo2(acc2[u]), lo2(acc2[9 + u]));
        *(float2*)&g_sigma[((size_t)n * OC + o) * HW + pix] = vv;

        float s = vv.x + vv.y;
        float q = vv.x * vv.x + vv.y * vv.y;
#pragma unroll
        for (int off = 16; off; off >>= 1) {
            s += __shfl_down_sync(0xffffffffu, s, off);
            q += __shfl_down_sync(0xffffffffu, q, off);
        }
        if ((tid & 31) == 0) { atomicAdd(&ssum[o], s); atomicAdd(&ssq[o], q); }
    }
    __syncthreads();
    if (tid < OC) { atomicAdd(&g_sum[tid], ssum[tid]); atomicAdd(&g_sumsq[tid], ssq[tid]); }
}

// Stats + self-reset (next graph replay sees zeros again).
__global__ void k_stats() {
    int o = threadIdx.x;
    if (o < OC) {
        float cnt = (float)((size_t)NN * HW);
        float m = g_sum[o] / cnt;
        float v = g_sumsq[o] / cnt - m * m;
        g_mean[o] = m;
        g_rstd[o] = rsqrtf(v + EPSF);
        g_sum[o] = 0.f;
        g_sumsq[o] = 0.f;
    }
}

// ---------------------------------------------------------------------------
// Stage 3: BN + softmax(18) + v_map + adaptive 3x3 filter. 4 pixels/thread.
// ---------------------------------------------------------------------------
__global__ void __launch_bounds__(128) k_apply(const float* __restrict__ y,
                                               const float* __restrict__ gamma,
                                               const float* __restrict__ beta,
                                               float* __restrict__ out) {
    int tx = threadIdx.x, ty = threadIdx.y;
    int w0 = (blockIdx.x * 32 + tx) * 4;
    int h0 = blockIdx.y * 4 + ty;
    int n  = blockIdx.z;
    size_t pix = (size_t)h0 * WW + w0;

    float4 s4[OC];
    float4 mx = make_float4(-1e30f, -1e30f, -1e30f, -1e30f);
#pragma unroll
    for (int o = 0; o < OC; o++) {
        float4 x = *(const float4*)&g_sigma[((size_t)n * OC + o) * HW + pix];
        float sc = g_rstd[o] * __ldg(&gamma[o]);
        float m  = g_mean[o], b = __ldg(&beta[o]);
        x.x = (x.x - m) * sc + b; x.y = (x.y - m) * sc + b;
        x.z = (x.z - m) * sc + b; x.w = (x.w - m) * sc + b;
        s4[o] = x;
        mx.x = fmaxf(mx.x, x.x); mx.y = fmaxf(mx.y, x.y);
        mx.z = fmaxf(mx.z, x.z); mx.w = fmaxf(mx.w, x.w);
    }
    float4 sum = make_float4(0.f, 0.f, 0.f, 0.f);
#pragma unroll
    for (int o = 0; o < OC; o++) {
        s4[o].x = __expf(s4[o].x - mx.x); sum.x += s4[o].x;
        s4[o].y = __expf(s4[o].y - mx.y); sum.y += s4[o].y;
        s4[o].z = __expf(s4[o].z - mx.z); sum.z += s4[o].z;
        s4[o].w = __expf(s4[o].w - mx.w); sum.w += s4[o].w;
    }
    float4 inv = make_float4(1.f / sum.x, 1.f / sum.y, 1.f / sum.z, 1.f / sum.w);
#pragma unroll
    for (int o = 0; o < OC; o++) {
        s4[o].x *= inv.x; s4[o].y *= inv.y; s4[o].z *= inv.z; s4[o].w *= inv.w;
    }

    float* vmap = out + (size_t)NN * CC * HW;
#pragma unroll
    for (int o = 0; o < OC; o++)
        *(float4*)&vmap[((size_t)n * OC + o) * HW + pix] = s4[o];

    int rh[3];
#pragma unroll
    for (int i = 0; i < 3; i++) rh[i] = refl(h0 + i - 1, HH);
    int wl = refl(w0 - 1, WW);
    int wr = refl(w0 + 4, WW);

#pragma unroll
    for (int g = 0; g < 2; g++) {
#pragma unroll 2
        for (int cg = 0; cg < 32; cg++) {
            int c = g * 32 + cg;
            const float* yc = y + ((size_t)(n * CC + c)) * HW;
            float4 acc = make_float4(0.f, 0.f, 0.f, 0.f);
#pragma unroll
            for (int i = 0; i < 3; i++) {
                const float* row = yc + rh[i] * WW;
                float4 m = __ldg((const float4*)(row + w0));
                float v[6];
                v[0] = __ldg(&row[wl]); v[1] = m.x; v[2] = m.y;
                v[3] = m.z; v[4] = m.w; v[5] = __ldg(&row[wr]);
#pragma unroll
                for (int j = 0; j < 3; j++) {
                    float4 sw = s4[g * 9 + i * 3 + j];
                    acc.x += v[0 + j] * sw.x;
                    acc.y += v[1 + j] * sw.y;
                    acc.z += v[2 + j] * sw.z;
                    acc.w += v[3 + j] * sw.w;
                }
            }
            *(float4*)&out[((size_t)(n * CC + c)) * HW + pix] = acc;
        }
    }
}

extern "C" void kernel_launch(void* const* d_in, const int* in_sizes, int n_in,
                              void* d_out, int out_size) {
    const float* y     = (const float*)d_in[0];
    const float* w     = (const float*)d_in[1];
    const float* gamma = (const float*)d_in[2];
    const float* beta  = (const float*)d_in[3];
    float* out = (float*)d_out;

    dim3 cblk(32, 4), cgrd(WW / 64, HH / 4, NN);   // 4 x 64 x 4 = 1024 CTAs
    k_conv<<<cgrd, cblk>>>(y, w);
    k_stats<<<1, 32>>>();

    dim3 ablk(32, 4), agrd(WW / 128, HH / 4, NN);
    k_apply<<<agrd, ablk>>>(y, gamma, beta, out);
}